// round 7
// baseline (speedup 1.0000x reference)
#include <cuda_runtime.h>
#include <cstdint>

// Problem constants
#define HH 1024
#define WW 1024
#define NIMG 6                 // 2 batch * 3 channels
#define NPIX (NIMG*HH*WW)      // 6291456
#define EPSV 0.001f
#define RR 16                  // output rows per thread in conv
#define NRED 888               // reduction blocks (6*148)

typedef unsigned long long u64;

// ---------------- device scratch (static, allocation-free) ----------------
__device__ float g_clip[NPIX];
__device__ float g_tmp[NPIX];
__device__ float g_tmpT[NPIX];
__device__ float g_acc[NPIX];
__device__ u64   g_kern2u[2304];   // duplicated {k,k} coeffs, zero padded
__device__ double g_part[NRED*4];

// ---------------- helpers ----------------
__device__ __forceinline__ u64 ffma2(u64 a, u64 b, u64 c) {
    u64 d;
    asm("fma.rn.f32x2 %0, %1, %2, %3;" : "=l"(d) : "l"(a), "l"(b), "l"(c));
    return d;
}

__device__ __forceinline__ int refl1024(int s) {
    s = (s < 0) ? -s : s;
    return (s > 1023) ? (2046 - s) : s;
}

// ---------------- 1: build normalized Gaussian kernels ----------------
// Layout per sigma in g_kern2u: [16 zeros][ks dup coeffs][48 zeros], len = ks+64
__global__ void init_kernels_k() {
    const float sigmas[3] = {15.f, 80.f, 250.f};
    const int   kss[3]    = {91, 481, 1501};
    const int   koffs[3]  = {0, 155, 700};
    int sig = blockIdx.x;
    float sigma = sigmas[sig];
    int ks = kss[sig], off = koffs[sig], len = ks + 64;

    __shared__ float buf[1504];
    __shared__ float red[512];
    int tid = threadIdx.x;

    float part = 0.f;
    for (int i = tid; i < ks; i += 512) {
        float x = (float)i - (float)(ks - 1) * 0.5f;
        float t = x / sigma;
        float e = expf(-0.5f * t * t);
        buf[i] = e;
        part += e;
    }
    red[tid] = part;
    __syncthreads();
    for (int s = 256; s > 0; s >>= 1) {
        if (tid < s) red[tid] += red[tid + s];
        __syncthreads();
    }
    float inv = 1.0f / red[0];
    for (int i = tid; i < len; i += 512) {
        float v = (i >= 16 && i < 16 + ks) ? buf[i - 16] * inv : 0.f;
        unsigned int b = __float_as_uint(v);
        g_kern2u[off + i] = ((u64)b << 32) | (u64)b;
    }
}

// ---------------- 2: clip input once ----------------
__global__ void clip_k(const float* __restrict__ in) {
    for (int i = blockIdx.x * blockDim.x + threadIdx.x; i < NPIX;
         i += gridDim.x * blockDim.x) {
        float x = in[i];
        g_clip[i] = fminf(fmaxf(x, EPSV), 1.0f);
    }
}

// ---------------- 3: vertical 1D Gaussian conv (leading-stride dim) ----------------
// Each thread: RR consecutive output rows x 2 columns (f32x2).
// Coefficient ring buffer cw[RR] in registers, all indices compile-time.
__global__ void __launch_bounds__(128, 4)
conv_v_k(const u64* __restrict__ src, u64* __restrict__ dst,
         int koff, int klen, int p) {
    extern __shared__ u64 ksh[];
    for (int i = threadIdx.x; i < klen; i += 128) ksh[i] = g_kern2u[koff + i];
    __syncthreads();

    int cp = blockIdx.x * 128 + threadIdx.x;       // column-pair index 0..511
    int r0 = blockIdx.y * RR;
    const u64* s0 = src + (size_t)blockIdx.z * (HH * WW / 2);

    u64 acc[RR], cw[RR];
#pragma unroll
    for (int j = 0; j < RR; j++) { acc[j] = 0ULL; cw[j] = 0ULL; }

    int S  = 2 * p + RR;
    int S2 = ((S + RR - 1) / RR) * RR;             // multiple of RR

    cw[0] = ksh[16];                               // kpad[16] = k[0]
    u64 v = s0[(size_t)refl1024(r0 - p) * 512 + cp];

    for (int step = 0; step < S2; step += RR) {
#pragma unroll
        for (int u = 0; u < RR; u++) {
            // prefetch next coeff + next pixel (consumed after this step's FMAs)
            u64 kn = ksh[16 + step + u + 1];
            int sn = r0 - p + step + u + 1;
            u64 vn = s0[(size_t)refl1024(sn) * 512 + cp];
#pragma unroll
            for (int j = 0; j < RR; j++)
                acc[j] = ffma2(cw[(u - j) & (RR - 1)], v, acc[j]);
            cw[(u + 1) & (RR - 1)] = kn;
            v = vn;
        }
    }

    u64* d0 = dst + (size_t)blockIdx.z * (HH * WW / 2);
#pragma unroll
    for (int j = 0; j < RR; j++) d0[(size_t)(r0 + j) * 512 + cp] = acc[j];
}

// ---------------- 4: tiled transpose ----------------
__global__ void transpose_k(const float* __restrict__ src, float* __restrict__ dst) {
    __shared__ float tile[32][33];
    size_t base = (size_t)blockIdx.z * HH * WW;
    int x  = blockIdx.x * 32 + threadIdx.x;
    int y0 = blockIdx.y * 32 + threadIdx.y;
#pragma unroll
    for (int dy = 0; dy < 32; dy += 8)
        tile[threadIdx.y + dy][threadIdx.x] = src[base + (size_t)(y0 + dy) * WW + x];
    __syncthreads();
    int x2 = blockIdx.y * 32 + threadIdx.x;
    int y2 = blockIdx.x * 32 + threadIdx.y;
#pragma unroll
    for (int dy = 0; dy < 32; dy += 8)
        dst[base + (size_t)(y2 + dy) * WW + x2] = tile[threadIdx.x][threadIdx.y + dy];
}

// ---------------- 5: transpose + log + accumulate into g_acc ----------------
// srcT[c][r] holds blur; write g_acc[r][c] (+)= log(max(blur, EPS))
__global__ void translog_acc_k(const float* __restrict__ srcT, int first) {
    __shared__ float tile[32][33];
    size_t base = (size_t)blockIdx.z * HH * WW;
    int x  = blockIdx.x * 32 + threadIdx.x;
    int y0 = blockIdx.y * 32 + threadIdx.y;
#pragma unroll
    for (int dy = 0; dy < 32; dy += 8) {
        float vv = srcT[base + (size_t)(y0 + dy) * WW + x];
        tile[threadIdx.y + dy][threadIdx.x] = logf(fmaxf(vv, EPSV));
    }
    __syncthreads();
    int x2 = blockIdx.y * 32 + threadIdx.x;
    int y2 = blockIdx.x * 32 + threadIdx.y;
#pragma unroll
    for (int dy = 0; dy < 32; dy += 8) {
        size_t o = base + (size_t)(y2 + dy) * WW + x2;
        float t = tile[threadIdx.x][threadIdx.y + dy];
        g_acc[o] = first ? t : (g_acc[o] + t);
    }
}

// ---------------- 6: finalize reflectance / illumination ----------------
__global__ void finalize_k(const float* __restrict__ in,
                           float* __restrict__ orefl, float* __restrict__ oil) {
    for (int i = blockIdx.x * blockDim.x + threadIdx.x; i < NPIX;
         i += gridDim.x * blockDim.x) {
        float x = in[i];
        float lmax  = logf(fmaxf(x, EPSV));
        float lclip = (x > 1.0f) ? 0.0f : lmax;   // log(min(max(x,eps),1))
        float il3  = g_acc[i] * (1.0f / 3.0f);    // mean log blur
        float refl = lclip - il3;
        orefl[i] = refl;
        oil[i]   = lmax - refl;                   // = log(max(x,eps)) - reflectance
    }
}

// ---------------- 7: gradient abs-sum reduction (deterministic) ----------------
__global__ void grad_k(const float* __restrict__ refl, const float* __restrict__ il) {
    double a0 = 0, a1 = 0, a2 = 0, a3 = 0;
    for (int i = blockIdx.x * blockDim.x + threadIdx.x; i < NPIX;
         i += gridDim.x * blockDim.x) {
        int rc = i & (HH * WW - 1);
        int r = rc >> 10, c = rc & 1023;
        float fr = refl[i], fi = il[i];
        if (c < WW - 1) { a0 += fabsf(fr - refl[i + 1]);  a2 += fabsf(fi - il[i + 1]); }
        if (r < HH - 1) { a1 += fabsf(fr - refl[i + WW]); a3 += fabsf(fi - il[i + WW]); }
    }
    __shared__ double sd[256];
    int tid = threadIdx.x;
    double vals[4] = {a0, a1, a2, a3};
    for (int k = 0; k < 4; k++) {
        sd[tid] = vals[k];
        __syncthreads();
        for (int s = 128; s > 0; s >>= 1) {
            if (tid < s) sd[tid] += sd[tid + s];
            __syncthreads();
        }
        if (tid == 0) g_part[blockIdx.x * 4 + k] = sd[0];
        __syncthreads();
    }
}

__global__ void scalar_k(float* __restrict__ out) {
    __shared__ double sd[256];
    __shared__ double tot[4];
    int tid = threadIdx.x;
    double s[4] = {0, 0, 0, 0};
    for (int i = tid; i < NRED; i += 256) {
        s[0] += g_part[i * 4 + 0];
        s[1] += g_part[i * 4 + 1];
        s[2] += g_part[i * 4 + 2];
        s[3] += g_part[i * 4 + 3];
    }
    for (int k = 0; k < 4; k++) {
        sd[tid] = s[k];
        __syncthreads();
        for (int st = 128; st > 0; st >>= 1) {
            if (tid < st) sd[tid] += sd[tid + st];
            __syncthreads();
        }
        if (tid == 0) tot[k] = sd[0];
        __syncthreads();
    }
    if (tid == 0) {
        double denx = (double)NIMG * HH * (WW - 1);
        double deny = (double)NIMG * (HH - 1) * WW;
        double detail = tot[0] / denx + tot[1] / deny;
        double smooth = tot[2] / denx + tot[3] / deny;
        out[0] = (float)(0.0 * detail + 1.0 * smooth);  // DETAIL_W=0, ILLUM_W=1
        out[1] = (float)detail;
        out[2] = (float)smooth;
    }
}

// ---------------- launch ----------------
extern "C" void kernel_launch(void* const* d_in, const int* in_sizes, int n_in,
                              void* d_out, int out_size) {
    const float* input = (const float*)d_in[0];
    float* out = (float*)d_out;

    float *clipP = nullptr, *tmpP = nullptr, *tmpTP = nullptr;
    cudaGetSymbolAddress((void**)&clipP, g_clip);
    cudaGetSymbolAddress((void**)&tmpP,  g_tmp);
    cudaGetSymbolAddress((void**)&tmpTP, g_tmpT);

    init_kernels_k<<<3, 512>>>();
    clip_k<<<2048, 256>>>(input);

    const int kss[3]   = {91, 481, 1501};
    const int koffs[3] = {0, 155, 700};
    dim3 cg(4, 64, NIMG);
    dim3 tg(32, 32, NIMG);
    dim3 tb(32, 8);

    for (int s = 0; s < 3; s++) {
        int ks = kss[s], p = ks / 2, klen = ks + 64;
        size_t sh = (size_t)klen * 8;
        // vertical blur of clipped image
        conv_v_k<<<cg, 128, sh>>>((const u64*)clipP, (u64*)tmpP, koffs[s], klen, p);
        // transpose, blur again (= horizontal), then log+accumulate back transposed
        transpose_k<<<tg, tb>>>(tmpP, tmpTP);
        conv_v_k<<<cg, 128, sh>>>((const u64*)tmpTP, (u64*)tmpP, koffs[s], klen, p);
        translog_acc_k<<<tg, tb>>>(tmpP, s == 0 ? 1 : 0);
    }

    finalize_k<<<2048, 256>>>(input, out + 3, out + 3 + NPIX);
    grad_k<<<NRED, 256>>>(out + 3, out + 3 + NPIX);
    scalar_k<<<1, 256>>>(out);
}

// round 11
// speedup vs baseline: 3.4513x; 3.4513x over previous
#include <cuda_runtime.h>
#include <cstdint>

// Problem constants
#define HH 1024
#define WW 1024
#define NIMG 6                 // 2 batch * 3 channels
#define NPIX (NIMG*HH*WW)      // 6291456
#define EPSV 0.001f
#define RR 16                  // output rows per thread in fine conv
#define NRED 888               // reduction blocks

// Fine sigma=15
#define KS15 91
#define P15  45
#define KLEN15 (KS15+64)       // 155 (16 zero head + 91 + 48 zero tail)
#define S2_15 112              // ceil((2*P15+RR)/RR)*RR

// Coarse grids
#define C8  128                // downsample s=8  (sigma=80)
#define C16 64                 // downsample s=16 (sigma=250)
#define KS80  61               // sigma_c = 9.987558
#define P80   30
#define KS250 95               // sigma_c = 15.617008
#define P250  47

typedef unsigned long long u64;

// ---------------- device scratch (static, allocation-free) ----------------
__device__ float g_tmp[NPIX];
__device__ float g_tmpT[NPIX];
__device__ float g_h8[NIMG*HH*C8];         // horizontal 8-box means
__device__ float g_c8a[NIMG*C8*C8];
__device__ float g_c8b[NIMG*C8*C8];
__device__ float g_c16a[NIMG*C16*C16];
__device__ float g_c16b[NIMG*C16*C16];
__device__ u64   g_kern2u[256];            // fine coeffs dup {k,k}, zero padded
__device__ float g_kc80[KS80];
__device__ float g_kc250[KS250];
__device__ double g_part[NRED*4];

// ---------------- helpers ----------------
__device__ __forceinline__ u64 ffma2(u64 a, u64 b, u64 c) {
    u64 d;
    asm("fma.rn.f32x2 %0, %1, %2, %3;" : "=l"(d) : "l"(a), "l"(b), "l"(c));
    return d;
}

__device__ __forceinline__ int refl1024(int s) {
    s = (s < 0) ? -s : s;
    return (s > 1023) ? (2046 - s) : s;
}

__device__ __forceinline__ u64 clip2(u64 x) {
    float a = __uint_as_float((unsigned)x);
    float b = __uint_as_float((unsigned)(x >> 32));
    a = fminf(fmaxf(a, EPSV), 1.0f);
    b = fminf(fmaxf(b, EPSV), 1.0f);
    return ((u64)__float_as_uint(b) << 32) | (u64)__float_as_uint(a);
}

// Bilinear upsample of coarse grid g (CxC), coarse centers at j*s+(s-1)/2.
// Edge clamping == even symmetry of the smooth field about the border.
__device__ __forceinline__ float bilerp(const float* __restrict__ g, int C,
                                        float inv, float half, int y, int x) {
    float ty = ((float)y - half) * inv;
    float tx = ((float)x - half) * inv;
    float fy = floorf(ty), fx = floorf(tx);
    float wy = ty - fy,    wx = tx - fx;
    int jy = (int)fy, jx = (int)fx;
    int y0 = max(jy, 0), y1 = min(jy + 1, C - 1);
    int x0 = max(jx, 0), x1 = min(jx + 1, C - 1);
    float v00 = g[y0 * C + x0], v01 = g[y0 * C + x1];
    float v10 = g[y1 * C + x0], v11 = g[y1 * C + x1];
    float a = v00 + wx * (v01 - v00);
    float b = v10 + wx * (v11 - v10);
    return a + wy * (b - a);
}

// ---------------- 1: build normalized Gaussian kernels ----------------
__global__ void init_kernels_k() {
    const float sigmas[3] = {15.f, 9.987558f, 15.617008f};
    const int   kss[3]    = {KS15, KS80, KS250};
    int sig = blockIdx.x;
    float sigma = sigmas[sig];
    int ks = kss[sig];

    __shared__ float buf[128];
    __shared__ float red[512];
    int tid = threadIdx.x;

    float part = 0.f;
    if (tid < ks) {
        float x = (float)tid - (float)(ks - 1) * 0.5f;
        float t = x / sigma;
        float e = expf(-0.5f * t * t);
        buf[tid] = e;
        part = e;
    }
    red[tid] = part;
    __syncthreads();
    for (int s = 256; s > 0; s >>= 1) {
        if (tid < s) red[tid] += red[tid + s];
        __syncthreads();
    }
    float inv = 1.0f / red[0];

    if (sig == 0) {
        for (int i = tid; i < KLEN15; i += 512) {
            float v = (i >= 16 && i < 16 + ks) ? buf[i - 16] * inv : 0.f;
            unsigned int b = __float_as_uint(v);
            g_kern2u[i] = ((u64)b << 32) | (u64)b;
        }
    } else if (sig == 1) {
        if (tid < ks) g_kc80[tid] = buf[tid] * inv;
    } else {
        if (tid < ks) g_kc250[tid] = buf[tid] * inv;
    }
}

// ---------------- 2: downsampling (clip fused) ----------------
__global__ void ds8h_k(const float* __restrict__ in) {
    int i = blockIdx.x * blockDim.x + threadIdx.x;
    if (i >= NIMG * HH * C8) return;
    int row = i >> 7;
    int cx  = i & 127;
    const float4* q = (const float4*)(in + (size_t)row * WW + cx * 8);
    float4 a = q[0], b = q[1];
    float s =
        fminf(fmaxf(a.x, EPSV), 1.f) + fminf(fmaxf(a.y, EPSV), 1.f) +
        fminf(fmaxf(a.z, EPSV), 1.f) + fminf(fmaxf(a.w, EPSV), 1.f) +
        fminf(fmaxf(b.x, EPSV), 1.f) + fminf(fmaxf(b.y, EPSV), 1.f) +
        fminf(fmaxf(b.z, EPSV), 1.f) + fminf(fmaxf(b.w, EPSV), 1.f);
    g_h8[i] = s * 0.125f;
}

__global__ void ds8v_k() {
    int i = blockIdx.x * blockDim.x + threadIdx.x;
    if (i >= NIMG * C8 * C8) return;
    int img = i / (C8 * C8);
    int r   = i % (C8 * C8);
    int cy = r / C8, cx = r % C8;
    const float* p = g_h8 + ((size_t)img * HH + cy * 8) * C8 + cx;
    float s = 0.f;
#pragma unroll
    for (int t = 0; t < 8; t++) s += p[t * C8];
    g_c8a[i] = s * 0.125f;
}

__global__ void ds16_k() {
    int i = blockIdx.x * blockDim.x + threadIdx.x;
    if (i >= NIMG * C16 * C16) return;
    int img = i / (C16 * C16);
    int r   = i % (C16 * C16);
    int cy = r / C16, cx = r % C16;
    const float* p = g_c8a + (size_t)img * C8 * C8 + (size_t)(cy * 2) * C8 + cx * 2;
    g_c16a[i] = 0.25f * (p[0] + p[1] + p[C8] + p[C8 + 1]);
}

// ---------------- 3: coarse separable conv, symmetric padding ----------------
__global__ void cconv_k(const float* __restrict__ src, float* __restrict__ dst,
                        const float* __restrict__ kc, int C, int ks, int p, int horiz) {
    __shared__ float kk[128];
    for (int i = threadIdx.x; i < ks; i += blockDim.x) kk[i] = kc[i];
    __syncthreads();
    int img = blockIdx.y;
    int idx = blockIdx.x * blockDim.x + threadIdx.x;
    if (idx >= C * C) return;
    int y = idx / C, x = idx % C;
    const float* s0 = src + (size_t)img * C * C;
    float acc = 0.f;
    if (horiz) {
        for (int t = 0; t < ks; t++) {
            int s = x - p + t;
            s = (s < 0) ? (-1 - s) : s;
            s = (s >= C) ? (2 * C - 1 - s) : s;
            acc += kk[t] * s0[y * C + s];
        }
    } else {
        for (int t = 0; t < ks; t++) {
            int s = y - p + t;
            s = (s < 0) ? (-1 - s) : s;
            s = (s >= C) ? (2 * C - 1 - s) : s;
            acc += kk[t] * s0[s * C + x];
        }
    }
    dst[(size_t)img * C * C + idx] = acc;
}

// ---------------- 4: fine vertical conv (sigma=15), ring buffer, f32x2 ----------------
template<int DOCLIP>
__global__ void __launch_bounds__(128, 4)
conv_v_k(const u64* __restrict__ src, u64* __restrict__ dst) {
    __shared__ u64 ksh[KLEN15];
    for (int i = threadIdx.x; i < KLEN15; i += 128) ksh[i] = g_kern2u[i];
    __syncthreads();

    int cp = blockIdx.x * 128 + threadIdx.x;       // column-pair 0..511
    int r0 = blockIdx.y * RR;
    const u64* s0 = src + (size_t)blockIdx.z * (HH * WW / 2);

    u64 acc[RR], cw[RR];
#pragma unroll
    for (int j = 0; j < RR; j++) { acc[j] = 0ULL; cw[j] = 0ULL; }

    cw[0] = ksh[16];
    u64 v = s0[(size_t)refl1024(r0 - P15) * 512 + cp];
    if (DOCLIP) v = clip2(v);

    for (int step = 0; step < S2_15; step += RR) {
#pragma unroll
        for (int u = 0; u < RR; u++) {
            u64 kn = ksh[16 + step + u + 1];
            int sn = r0 - P15 + step + u + 1;
            u64 vn = s0[(size_t)refl1024(sn) * 512 + cp];
#pragma unroll
            for (int j = 0; j < RR; j++)
                acc[j] = ffma2(cw[(u - j) & (RR - 1)], v, acc[j]);
            cw[(u + 1) & (RR - 1)] = kn;
            v = DOCLIP ? clip2(vn) : vn;
        }
    }

    u64* d0 = dst + (size_t)blockIdx.z * (HH * WW / 2);
#pragma unroll
    for (int j = 0; j < RR; j++) d0[(size_t)(r0 + j) * 512 + cp] = acc[j];
}

// ---------------- 5: tiled transpose ----------------
__global__ void transpose_k(const float* __restrict__ src, float* __restrict__ dst) {
    __shared__ float tile[32][33];
    size_t base = (size_t)blockIdx.z * HH * WW;
    int x  = blockIdx.x * 32 + threadIdx.x;
    int y0 = blockIdx.y * 32 + threadIdx.y;
#pragma unroll
    for (int dy = 0; dy < 32; dy += 8)
        tile[threadIdx.y + dy][threadIdx.x] = src[base + (size_t)(y0 + dy) * WW + x];
    __syncthreads();
    int x2 = blockIdx.y * 32 + threadIdx.x;
    int y2 = blockIdx.x * 32 + threadIdx.y;
#pragma unroll
    for (int dy = 0; dy < 32; dy += 8)
        dst[base + (size_t)(y2 + dy) * WW + x2] = tile[threadIdx.x][threadIdx.y + dy];
}

// ---------------- 6: fused finalize: transpose b15T + upsample + logs ----------------
__global__ void final_k(const float* __restrict__ in, const float* __restrict__ b15T,
                        float* __restrict__ orefl, float* __restrict__ oil) {
    __shared__ float tile[32][33];
    int img = blockIdx.z;
    size_t base = (size_t)img * HH * WW;
    const float* c80  = g_c8a  + (size_t)img * C8 * C8;
    const float* c250 = g_c16a + (size_t)img * C16 * C16;

    int x  = blockIdx.x * 32 + threadIdx.x;
    int y0 = blockIdx.y * 32 + threadIdx.y;
#pragma unroll
    for (int dy = 0; dy < 32; dy += 8)
        tile[threadIdx.y + dy][threadIdx.x] = b15T[base + (size_t)(y0 + dy) * WW + x];
    __syncthreads();

    int x2  = blockIdx.y * 32 + threadIdx.x;
    int y2b = blockIdx.x * 32 + threadIdx.y;
#pragma unroll
    for (int dy = 0; dy < 32; dy += 8) {
        int y2 = y2b + dy;
        size_t o = base + (size_t)y2 * WW + x2;
        float b15  = tile[threadIdx.x][threadIdx.y + dy];
        float u80  = bilerp(c80,  C8,  0.125f,  3.5f, y2, x2);
        float u250 = bilerp(c250, C16, 0.0625f, 7.5f, y2, x2);
        float il = (logf(fmaxf(b15, EPSV)) + logf(fmaxf(u80, EPSV)) +
                    logf(fmaxf(u250, EPSV))) * (1.0f / 3.0f);
        float xv = in[o];
        float lmax  = logf(fmaxf(xv, EPSV));
        float lclip = (xv > 1.0f) ? 0.0f : lmax;   // log(clip(x, eps, 1))
        float refl = lclip - il;
        orefl[o] = refl;
        oil[o]   = lmax - refl;
    }
}

// ---------------- 7: gradient abs-sum reduction (deterministic) ----------------
__global__ void grad_k(const float* __restrict__ refl, const float* __restrict__ il) {
    double a0 = 0, a1 = 0, a2 = 0, a3 = 0;
    for (int i = blockIdx.x * blockDim.x + threadIdx.x; i < NPIX;
         i += gridDim.x * blockDim.x) {
        int rc = i & (HH * WW - 1);
        int r = rc >> 10, c = rc & 1023;
        float fr = refl[i], fi = il[i];
        if (c < WW - 1) { a0 += fabsf(fr - refl[i + 1]);  a2 += fabsf(fi - il[i + 1]); }
        if (r < HH - 1) { a1 += fabsf(fr - refl[i + WW]); a3 += fabsf(fi - il[i + WW]); }
    }
    __shared__ double sd[256];
    int tid = threadIdx.x;
    double vals[4] = {a0, a1, a2, a3};
    for (int k = 0; k < 4; k++) {
        sd[tid] = vals[k];
        __syncthreads();
        for (int s = 128; s > 0; s >>= 1) {
            if (tid < s) sd[tid] += sd[tid + s];
            __syncthreads();
        }
        if (tid == 0) g_part[blockIdx.x * 4 + k] = sd[0];
        __syncthreads();
    }
}

__global__ void scalar_k(float* __restrict__ out) {
    __shared__ double sd[256];
    __shared__ double tot[4];
    int tid = threadIdx.x;
    double s[4] = {0, 0, 0, 0};
    for (int i = tid; i < NRED; i += 256) {
        s[0] += g_part[i * 4 + 0];
        s[1] += g_part[i * 4 + 1];
        s[2] += g_part[i * 4 + 2];
        s[3] += g_part[i * 4 + 3];
    }
    for (int k = 0; k < 4; k++) {
        sd[tid] = s[k];
        __syncthreads();
        for (int st = 128; st > 0; st >>= 1) {
            if (tid < st) sd[tid] += sd[tid + st];
            __syncthreads();
        }
        if (tid == 0) tot[k] = sd[0];
        __syncthreads();
    }
    if (tid == 0) {
        double denx = (double)NIMG * HH * (WW - 1);
        double deny = (double)NIMG * (HH - 1) * WW;
        double detail = tot[0] / denx + tot[1] / deny;
        double smooth = tot[2] / denx + tot[3] / deny;
        out[0] = (float)(0.0 * detail + 1.0 * smooth);  // DETAIL_W=0, ILLUM_W=1
        out[1] = (float)detail;
        out[2] = (float)smooth;
    }
}

// ---------------- launch ----------------
extern "C" void kernel_launch(void* const* d_in, const int* in_sizes, int n_in,
                              void* d_out, int out_size) {
    const float* input = (const float*)d_in[0];
    float* out = (float*)d_out;

    float *tmpP = nullptr, *tmpTP = nullptr;
    float *c8aP = nullptr, *c8bP = nullptr, *c16aP = nullptr, *c16bP = nullptr;
    float *kc80P = nullptr, *kc250P = nullptr;
    cudaGetSymbolAddress((void**)&tmpP,   g_tmp);
    cudaGetSymbolAddress((void**)&tmpTP,  g_tmpT);
    cudaGetSymbolAddress((void**)&c8aP,   g_c8a);
    cudaGetSymbolAddress((void**)&c8bP,   g_c8b);
    cudaGetSymbolAddress((void**)&c16aP,  g_c16a);
    cudaGetSymbolAddress((void**)&c16bP,  g_c16b);
    cudaGetSymbolAddress((void**)&kc80P,  g_kc80);
    cudaGetSymbolAddress((void**)&kc250P, g_kc250);

    init_kernels_k<<<3, 512>>>();

    // coarse path: downsample (clip fused), 2 coarse blurs (symmetric padding)
    ds8h_k<<<(NIMG*HH*C8 + 255) / 256, 256>>>(input);
    ds8v_k<<<(NIMG*C8*C8 + 255) / 256, 256>>>();
    ds16_k<<<(NIMG*C16*C16 + 255) / 256, 256>>>();
    cconv_k<<<dim3(64, NIMG), 256>>>(c8aP,  c8bP,  kc80P,  C8,  KS80,  P80,  0);
    cconv_k<<<dim3(64, NIMG), 256>>>(c8bP,  c8aP,  kc80P,  C8,  KS80,  P80,  1);
    cconv_k<<<dim3(16, NIMG), 256>>>(c16aP, c16bP, kc250P, C16, KS250, P250, 0);
    cconv_k<<<dim3(16, NIMG), 256>>>(c16bP, c16aP, kc250P, C16, KS250, P250, 1);

    // fine path: sigma=15 exact separable conv (clip fused into pass 1)
    dim3 cg(4, 64, NIMG);
    dim3 tg(32, 32, NIMG);
    dim3 tb(32, 8);
    conv_v_k<1><<<cg, 128>>>((const u64*)input, (u64*)tmpP);
    transpose_k<<<tg, tb>>>(tmpP, tmpTP);
    conv_v_k<0><<<cg, 128>>>((const u64*)tmpTP, (u64*)tmpP);  // -> blur15 transposed

    // fused finalize + reductions
    final_k<<<tg, tb>>>(input, tmpP, out + 3, out + 3 + NPIX);
    grad_k<<<NRED, 256>>>(out + 3, out + 3 + NPIX);
    scalar_k<<<1, 256>>>(out);
}

// round 12
// speedup vs baseline: 7.6647x; 2.2208x over previous
#include <cuda_runtime.h>
#include <cstdint>

// Problem constants
#define HH 1024
#define WW 1024
#define NIMG 6                 // 2 batch * 3 channels
#define NPIX (NIMG*HH*WW)      // 6291456
#define EPSV 0.001f
#define RR 16                  // output rows per thread in fine conv
#define NTILE (32*32*NIMG)     // final_k blocks = 6144

// Fine sigma=15
#define KS15 91
#define P15  45
#define KLEN15 (KS15+64)       // 155 (16 zero head + 91 + 48 zero tail)
#define S2_15 112              // ceil((2*P15+RR)/RR)*RR

// Coarse grids
#define C8  128                // downsample s=8  (sigma=80)
#define C16 64                 // downsample s=16 (sigma=250)
#define KS80  61               // sigma_c = 9.987558
#define P80   30
#define KS250 95               // sigma_c = 15.617008
#define P250  47

typedef unsigned long long u64;

// ---------------- device scratch (static, allocation-free) ----------------
__device__ float g_tmp[NPIX];
__device__ float g_tmpT[NPIX];
__device__ float g_h8[NIMG*HH*C8];         // horizontal 8-box means
__device__ float g_c8a[NIMG*C8*C8];
__device__ float g_c8b[NIMG*C8*C8];
__device__ float g_c16a[NIMG*C16*C16];
__device__ float g_c16b[NIMG*C16*C16];
__device__ u64   g_kern2u[256];            // fine coeffs dup {k,k}, zero padded
__device__ float g_kc80[KS80];
__device__ float g_kc250[KS250];
__device__ double g_part[NTILE*4];

// ---------------- helpers ----------------
__device__ __forceinline__ u64 ffma2(u64 a, u64 b, u64 c) {
    u64 d;
    asm("fma.rn.f32x2 %0, %1, %2, %3;" : "=l"(d) : "l"(a), "l"(b), "l"(c));
    return d;
}

__device__ __forceinline__ int refl1024(int s) {
    s = (s < 0) ? -s : s;
    return (s > 1023) ? (2046 - s) : s;
}

__device__ __forceinline__ u64 clip2(u64 x) {
    float a = __uint_as_float((unsigned)x);
    float b = __uint_as_float((unsigned)(x >> 32));
    a = fminf(fmaxf(a, EPSV), 1.0f);
    b = fminf(fmaxf(b, EPSV), 1.0f);
    return ((u64)__float_as_uint(b) << 32) | (u64)__float_as_uint(a);
}

// Bilinear upsample of coarse grid g (CxC), coarse centers at j*s+(s-1)/2.
__device__ __forceinline__ float bilerp(const float* __restrict__ g, int C,
                                        float inv, float half, int y, int x) {
    float ty = ((float)y - half) * inv;
    float tx = ((float)x - half) * inv;
    float fy = floorf(ty), fx = floorf(tx);
    float wy = ty - fy,    wx = tx - fx;
    int jy = (int)fy, jx = (int)fx;
    int y0 = max(jy, 0), y1 = min(jy + 1, C - 1);
    int x0 = max(jx, 0), x1 = min(jx + 1, C - 1);
    float v00 = g[y0 * C + x0], v01 = g[y0 * C + x1];
    float v10 = g[y1 * C + x0], v11 = g[y1 * C + x1];
    float a = v00 + wx * (v01 - v00);
    float b = v10 + wx * (v11 - v10);
    return a + wy * (b - a);
}

// ---------------- 1: build normalized Gaussian kernels ----------------
__global__ void init_kernels_k() {
    const float sigmas[3] = {15.f, 9.987558f, 15.617008f};
    const int   kss[3]    = {KS15, KS80, KS250};
    int sig = blockIdx.x;
    float sigma = sigmas[sig];
    int ks = kss[sig];

    __shared__ float buf[128];
    __shared__ float red[512];
    int tid = threadIdx.x;

    float part = 0.f;
    if (tid < ks) {
        float x = (float)tid - (float)(ks - 1) * 0.5f;
        float t = x / sigma;
        float e = expf(-0.5f * t * t);
        buf[tid] = e;
        part = e;
    }
    red[tid] = part;
    __syncthreads();
    for (int s = 256; s > 0; s >>= 1) {
        if (tid < s) red[tid] += red[tid + s];
        __syncthreads();
    }
    float inv = 1.0f / red[0];

    if (sig == 0) {
        for (int i = tid; i < KLEN15; i += 512) {
            float v = (i >= 16 && i < 16 + ks) ? buf[i - 16] * inv : 0.f;
            unsigned int b = __float_as_uint(v);
            g_kern2u[i] = ((u64)b << 32) | (u64)b;
        }
    } else if (sig == 1) {
        if (tid < ks) g_kc80[tid] = buf[tid] * inv;
    } else {
        if (tid < ks) g_kc250[tid] = buf[tid] * inv;
    }
}

// ---------------- 2: downsampling (clip fused) ----------------
__global__ void ds8h_k(const float* __restrict__ in) {
    int i = blockIdx.x * blockDim.x + threadIdx.x;
    if (i >= NIMG * HH * C8) return;
    int row = i >> 7;
    int cx  = i & 127;
    const float4* q = (const float4*)(in + (size_t)row * WW + cx * 8);
    float4 a = q[0], b = q[1];
    float s =
        fminf(fmaxf(a.x, EPSV), 1.f) + fminf(fmaxf(a.y, EPSV), 1.f) +
        fminf(fmaxf(a.z, EPSV), 1.f) + fminf(fmaxf(a.w, EPSV), 1.f) +
        fminf(fmaxf(b.x, EPSV), 1.f) + fminf(fmaxf(b.y, EPSV), 1.f) +
        fminf(fmaxf(b.z, EPSV), 1.f) + fminf(fmaxf(b.w, EPSV), 1.f);
    g_h8[i] = s * 0.125f;
}

__global__ void ds8v_k() {
    int i = blockIdx.x * blockDim.x + threadIdx.x;
    if (i >= NIMG * C8 * C8) return;
    int img = i / (C8 * C8);
    int r   = i % (C8 * C8);
    int cy = r / C8, cx = r % C8;
    const float* p = g_h8 + ((size_t)img * HH + cy * 8) * C8 + cx;
    float s = 0.f;
#pragma unroll
    for (int t = 0; t < 8; t++) s += p[t * C8];
    g_c8a[i] = s * 0.125f;
}

__global__ void ds16_k() {
    int i = blockIdx.x * blockDim.x + threadIdx.x;
    if (i >= NIMG * C16 * C16) return;
    int img = i / (C16 * C16);
    int r   = i % (C16 * C16);
    int cy = r / C16, cx = r % C16;
    const float* p = g_c8a + (size_t)img * C8 * C8 + (size_t)(cy * 2) * C8 + cx * 2;
    g_c16a[i] = 0.25f * (p[0] + p[1] + p[C8] + p[C8 + 1]);
}

// ---------------- 3: coarse separable conv, symmetric padding ----------------
__global__ void cconv_k(const float* __restrict__ src, float* __restrict__ dst,
                        const float* __restrict__ kc, int C, int ks, int p, int horiz) {
    __shared__ float kk[128];
    for (int i = threadIdx.x; i < ks; i += blockDim.x) kk[i] = kc[i];
    __syncthreads();
    int img = blockIdx.y;
    int idx = blockIdx.x * blockDim.x + threadIdx.x;
    if (idx >= C * C) return;
    int y = idx / C, x = idx % C;
    const float* s0 = src + (size_t)img * C * C;
    float acc = 0.f;
    if (horiz) {
        for (int t = 0; t < ks; t++) {
            int s = x - p + t;
            s = (s < 0) ? (-1 - s) : s;
            s = (s >= C) ? (2 * C - 1 - s) : s;
            acc += kk[t] * s0[y * C + s];
        }
    } else {
        for (int t = 0; t < ks; t++) {
            int s = y - p + t;
            s = (s < 0) ? (-1 - s) : s;
            s = (s >= C) ? (2 * C - 1 - s) : s;
            acc += kk[t] * s0[s * C + x];
        }
    }
    dst[(size_t)img * C * C + idx] = acc;
}

// ---------------- 4: fine vertical conv (sigma=15), ring buffer, f32x2 ----------------
template<int DOCLIP>
__global__ void __launch_bounds__(128, 4)
conv_v_k(const u64* __restrict__ src, u64* __restrict__ dst) {
    __shared__ u64 ksh[KLEN15];
    for (int i = threadIdx.x; i < KLEN15; i += 128) ksh[i] = g_kern2u[i];
    __syncthreads();

    int cp = blockIdx.x * 128 + threadIdx.x;       // column-pair 0..511
    int r0 = blockIdx.y * RR;
    const u64* s0 = src + (size_t)blockIdx.z * (HH * WW / 2);

    u64 acc[RR], cw[RR];
#pragma unroll
    for (int j = 0; j < RR; j++) { acc[j] = 0ULL; cw[j] = 0ULL; }

    cw[0] = ksh[16];
    u64 v = s0[(size_t)refl1024(r0 - P15) * 512 + cp];
    if (DOCLIP) v = clip2(v);

    for (int step = 0; step < S2_15; step += RR) {
#pragma unroll
        for (int u = 0; u < RR; u++) {
            u64 kn = ksh[16 + step + u + 1];
            int sn = r0 - P15 + step + u + 1;
            u64 vn = s0[(size_t)refl1024(sn) * 512 + cp];
#pragma unroll
            for (int j = 0; j < RR; j++)
                acc[j] = ffma2(cw[(u - j) & (RR - 1)], v, acc[j]);
            cw[(u + 1) & (RR - 1)] = kn;
            v = DOCLIP ? clip2(vn) : vn;
        }
    }

    u64* d0 = dst + (size_t)blockIdx.z * (HH * WW / 2);
#pragma unroll
    for (int j = 0; j < RR; j++) d0[(size_t)(r0 + j) * 512 + cp] = acc[j];
}

// ---------------- 5: tiled transpose ----------------
__global__ void transpose_k(const float* __restrict__ src, float* __restrict__ dst) {
    __shared__ float tile[32][33];
    size_t base = (size_t)blockIdx.z * HH * WW;
    int x  = blockIdx.x * 32 + threadIdx.x;
    int y0 = blockIdx.y * 32 + threadIdx.y;
#pragma unroll
    for (int dy = 0; dy < 32; dy += 8)
        tile[threadIdx.y + dy][threadIdx.x] = src[base + (size_t)(y0 + dy) * WW + x];
    __syncthreads();
    int x2 = blockIdx.y * 32 + threadIdx.x;
    int y2 = blockIdx.x * 32 + threadIdx.y;
#pragma unroll
    for (int dy = 0; dy < 32; dy += 8)
        dst[base + (size_t)(y2 + dy) * WW + x2] = tile[threadIdx.x][threadIdx.y + dy];
}

// ---------------- 6: fused finalize + gradient reduction ----------------
// Tile 32x32 of output + 1 halo (right/bottom). Computes refl/il in shared,
// writes owned pixels, accumulates |grad| for owned pairs. No grad_k pass.
__global__ void __launch_bounds__(256)
final_k(const float* __restrict__ in, const float* __restrict__ b15T,
        float* __restrict__ orefl, float* __restrict__ oil) {
    __shared__ float sB[33][34];
    __shared__ float sR[33][34];
    __shared__ float sI[33][34];
    __shared__ float warpred[8][4];

    int img = blockIdx.z;
    size_t base = (size_t)img * HH * WW;
    const float* c80  = g_c8a  + (size_t)img * C8 * C8;
    const float* c250 = g_c16a + (size_t)img * C16 * C16;
    int X0 = blockIdx.x * 32;
    int Y0 = blockIdx.y * 32;
    int tid = threadIdx.x;

    // Loop A: load b15 (stored transposed) -> sB[y][x]; coalesced along y.
    for (int idx = tid; idx < 33 * 33; idx += 256) {
        int xo = idx / 33, yo = idx % 33;
        int gx = min(X0 + xo, HH - 1);
        int gy = min(Y0 + yo, HH - 1);
        sB[yo][xo] = b15T[base + (size_t)gx * WW + gy];
    }
    __syncthreads();

    // Loop B: compute refl / il for the 33x33 halo tile.
    for (int idx = tid; idx < 33 * 33; idx += 256) {
        int yo = idx / 33, xo = idx % 33;
        int gy = min(Y0 + yo, HH - 1);
        int gx = min(X0 + xo, WW - 1);
        float b15  = sB[yo][xo];
        float u80  = bilerp(c80,  C8,  0.125f,  3.5f, gy, gx);
        float u250 = bilerp(c250, C16, 0.0625f, 7.5f, gy, gx);
        float il3 = (logf(fmaxf(b15, EPSV)) + logf(fmaxf(u80, EPSV)) +
                     logf(fmaxf(u250, EPSV))) * (1.0f / 3.0f);
        float xv = in[base + (size_t)gy * WW + gx];
        float lmax  = logf(fmaxf(xv, EPSV));
        float lclip = fminf(lmax, 0.0f);          // log(clip(x, eps, 1))
        float refl = lclip - il3;
        sR[yo][xo] = refl;
        sI[yo][xo] = lmax - refl;
    }
    __syncthreads();

    // Loop C: write owned 32x32 + accumulate gradient abs-sums (float).
    float a0 = 0.f, a1 = 0.f, a2 = 0.f, a3 = 0.f;
    for (int idx = tid; idx < 32 * 32; idx += 256) {
        int yo = idx >> 5, xo = idx & 31;
        int gy = Y0 + yo, gx = X0 + xo;
        size_t o = base + (size_t)gy * WW + gx;
        float r = sR[yo][xo], i = sI[yo][xo];
        orefl[o] = r;
        oil[o]   = i;
        if (gx < WW - 1) { a0 += fabsf(r - sR[yo][xo + 1]); a2 += fabsf(i - sI[yo][xo + 1]); }
        if (gy < HH - 1) { a1 += fabsf(r - sR[yo + 1][xo]); a3 += fabsf(i - sI[yo + 1][xo]); }
    }

    // warp reduce
#pragma unroll
    for (int s = 16; s > 0; s >>= 1) {
        a0 += __shfl_down_sync(0xffffffffu, a0, s);
        a1 += __shfl_down_sync(0xffffffffu, a1, s);
        a2 += __shfl_down_sync(0xffffffffu, a2, s);
        a3 += __shfl_down_sync(0xffffffffu, a3, s);
    }
    int wid = tid >> 5, lid = tid & 31;
    if (lid == 0) {
        warpred[wid][0] = a0; warpred[wid][1] = a1;
        warpred[wid][2] = a2; warpred[wid][3] = a3;
    }
    __syncthreads();
    if (tid == 0) {
        double t0 = 0, t1 = 0, t2 = 0, t3 = 0;
#pragma unroll
        for (int w = 0; w < 8; w++) {
            t0 += (double)warpred[w][0]; t1 += (double)warpred[w][1];
            t2 += (double)warpred[w][2]; t3 += (double)warpred[w][3];
        }
        int bid = (img * 32 + blockIdx.y) * 32 + blockIdx.x;
        g_part[bid * 4 + 0] = t0; g_part[bid * 4 + 1] = t1;
        g_part[bid * 4 + 2] = t2; g_part[bid * 4 + 3] = t3;
    }
}

// ---------------- 7: scalar reduction ----------------
__global__ void scalar_k(float* __restrict__ out) {
    __shared__ double sd[256];
    __shared__ double tot[4];
    int tid = threadIdx.x;
    double s[4] = {0, 0, 0, 0};
    for (int i = tid; i < NTILE; i += 256) {
        s[0] += g_part[i * 4 + 0];
        s[1] += g_part[i * 4 + 1];
        s[2] += g_part[i * 4 + 2];
        s[3] += g_part[i * 4 + 3];
    }
    for (int k = 0; k < 4; k++) {
        sd[tid] = s[k];
        __syncthreads();
        for (int st = 128; st > 0; st >>= 1) {
            if (tid < st) sd[tid] += sd[tid + st];
            __syncthreads();
        }
        if (tid == 0) tot[k] = sd[0];
        __syncthreads();
    }
    if (tid == 0) {
        double denx = (double)NIMG * HH * (WW - 1);
        double deny = (double)NIMG * (HH - 1) * WW;
        double detail = tot[0] / denx + tot[1] / deny;
        double smooth = tot[2] / denx + tot[3] / deny;
        out[0] = (float)(0.0 * detail + 1.0 * smooth);  // DETAIL_W=0, ILLUM_W=1
        out[1] = (float)detail;
        out[2] = (float)smooth;
    }
}

// ---------------- launch ----------------
extern "C" void kernel_launch(void* const* d_in, const int* in_sizes, int n_in,
                              void* d_out, int out_size) {
    const float* input = (const float*)d_in[0];
    float* out = (float*)d_out;

    float *tmpP = nullptr, *tmpTP = nullptr;
    float *c8aP = nullptr, *c8bP = nullptr, *c16aP = nullptr, *c16bP = nullptr;
    float *kc80P = nullptr, *kc250P = nullptr;
    cudaGetSymbolAddress((void**)&tmpP,   g_tmp);
    cudaGetSymbolAddress((void**)&tmpTP,  g_tmpT);
    cudaGetSymbolAddress((void**)&c8aP,   g_c8a);
    cudaGetSymbolAddress((void**)&c8bP,   g_c8b);
    cudaGetSymbolAddress((void**)&c16aP,  g_c16a);
    cudaGetSymbolAddress((void**)&c16bP,  g_c16b);
    cudaGetSymbolAddress((void**)&kc80P,  g_kc80);
    cudaGetSymbolAddress((void**)&kc250P, g_kc250);

    init_kernels_k<<<3, 512>>>();

    // coarse path: downsample (clip fused), 2 coarse blurs (symmetric padding)
    ds8h_k<<<(NIMG*HH*C8 + 255) / 256, 256>>>(input);
    ds8v_k<<<(NIMG*C8*C8 + 255) / 256, 256>>>();
    ds16_k<<<(NIMG*C16*C16 + 255) / 256, 256>>>();
    cconv_k<<<dim3(64, NIMG), 256>>>(c8aP,  c8bP,  kc80P,  C8,  KS80,  P80,  0);
    cconv_k<<<dim3(64, NIMG), 256>>>(c8bP,  c8aP,  kc80P,  C8,  KS80,  P80,  1);
    cconv_k<<<dim3(16, NIMG), 256>>>(c16aP, c16bP, kc250P, C16, KS250, P250, 0);
    cconv_k<<<dim3(16, NIMG), 256>>>(c16bP, c16aP, kc250P, C16, KS250, P250, 1);

    // fine path: sigma=15 exact separable conv (clip fused into pass 1)
    dim3 cg(4, 64, NIMG);
    dim3 tg(32, 32, NIMG);
    dim3 tb(32, 8);
    conv_v_k<1><<<cg, 128>>>((const u64*)input, (u64*)tmpP);
    transpose_k<<<tg, tb>>>(tmpP, tmpTP);
    conv_v_k<0><<<cg, 128>>>((const u64*)tmpTP, (u64*)tmpP);  // -> blur15 transposed

    // fused finalize (+gradient reduction) and scalar pass
    final_k<<<dim3(32, 32, NIMG), 256>>>(input, tmpP, out + 3, out + 3 + NPIX);
    scalar_k<<<1, 256>>>(out);
}

// round 16
// speedup vs baseline: 8.1104x; 1.0581x over previous
#include <cuda_runtime.h>
#include <cstdint>

// Problem constants
#define HH 1024
#define WW 1024
#define NIMG 6                 // 2 batch * 3 channels
#define NPIX (NIMG*HH*WW)      // 6291456
#define EPSV 0.001f
#define RR 16                  // output rows per thread in fine conv
#define NTILE (32*32*NIMG)     // final_k blocks = 6144

// Fine sigma=15 (exact)
#define KS15 91
#define P15  45
#define KLEN15 (KS15+64)       // 155 (16 zero head + 91 + 48 zero tail)
#define S2_15 112              // ceil((2*P15+RR)/RR)*RR

// Coarse grids (sigma=80 on s=8, sigma=250 on s=16), variance-matched sigmas
#define C2  512
#define C8  128
#define C16 64
#define KS80  61               // sigma_c = 9.987558
#define P80   30
#define KS250 95               // sigma_c = 15.617008
#define P250  47

#define N2  (NIMG*C2*C2)
#define N8  (NIMG*C8*C8)
#define N16 (NIMG*C16*C16)

typedef unsigned long long u64;

// ---------------- device scratch (static, allocation-free) ----------------
__device__ float g_tmp[NPIX];
__device__ float g_tmpT[NPIX];
__device__ float g_s2a[N2];                // s=2 box means (clipped input)
__device__ float g_s2b[N2];                // merged log u80 + log u250
__device__ float g_c8a[N8];
__device__ float g_c8b[N8];
__device__ float g_c16a[N16];
__device__ float g_c16b[N16];
__device__ u64   g_kern2u[256];            // fine dup {k,k} coeffs, zero padded
__device__ float g_kc80[KS80];
__device__ float g_kc250[KS250];
__device__ double g_part[NTILE*4];

// ---------------- helpers ----------------
__device__ __forceinline__ u64 ffma2(u64 a, u64 b, u64 c) {
    u64 d;
    asm("fma.rn.f32x2 %0, %1, %2, %3;" : "=l"(d) : "l"(a), "l"(b), "l"(c));
    return d;
}

__device__ __forceinline__ int refl1024(int s) {
    s = (s < 0) ? -s : s;                   // np.pad 'reflect' about edge pixel
    return (s > 1023) ? (2046 - s) : s;
}

__device__ __forceinline__ int reflC(int s, int C) {
    s = (s < 0) ? (-1 - s) : s;             // symmetric (half-sample) padding
    return (s >= C) ? (2 * C - 1 - s) : s;
}

__device__ __forceinline__ u64 clip2(u64 x) {
    float a = __uint_as_float((unsigned)x);
    float b = __uint_as_float((unsigned)(x >> 32));
    a = fminf(fmaxf(a, EPSV), 1.0f);
    b = fminf(fmaxf(b, EPSV), 1.0f);
    return ((u64)__float_as_uint(b) << 32) | (u64)__float_as_uint(a);
}

// Bilinear sample of coarse grid (CxC), coarse centers at j*s+(s-1)/2.
__device__ __forceinline__ float bilerpF(const float* __restrict__ g, int C,
                                         float inv, float half, float yf, float xf) {
    float ty = (yf - half) * inv;
    float tx = (xf - half) * inv;
    float fy = floorf(ty), fx = floorf(tx);
    float wy = ty - fy,    wx = tx - fx;
    int jy = (int)fy, jx = (int)fx;
    int y0 = max(jy, 0), y1 = min(jy + 1, C - 1);
    int x0 = max(jx, 0), x1 = min(jx + 1, C - 1);
    float v00 = g[y0 * C + x0], v01 = g[y0 * C + x1];
    float v10 = g[y1 * C + x0], v11 = g[y1 * C + x1];
    float a = v00 + wx * (v01 - v00);
    float b = v10 + wx * (v11 - v10);
    return a + wy * (b - a);
}

// ---------------- 1: build normalized Gaussian kernels ----------------
__global__ void init_kernels_k() {
    const float sigmas[3] = {15.f, 9.987558f, 15.617008f};
    const int   kss[3]    = {KS15, KS80, KS250};
    int sig = blockIdx.x;
    float sigma = sigmas[sig];
    int ks = kss[sig];

    __shared__ float buf[128];
    __shared__ float red[512];
    int tid = threadIdx.x;

    float part = 0.f;
    if (tid < ks) {
        float x = (float)tid - (float)(ks - 1) * 0.5f;
        float t = x / sigma;
        float e = expf(-0.5f * t * t);
        buf[tid] = e;
        part = e;
    }
    red[tid] = part;
    __syncthreads();
    for (int s = 256; s > 0; s >>= 1) {
        if (tid < s) red[tid] += red[tid + s];
        __syncthreads();
    }
    float inv = 1.0f / red[0];

    if (sig == 0) {
        for (int i = tid; i < KLEN15; i += 512) {
            float v = (i >= 16 && i < 16 + ks) ? buf[i - 16] * inv : 0.f;
            unsigned int b = __float_as_uint(v);
            g_kern2u[i] = ((u64)b << 32) | (u64)b;
        }
    } else if (sig == 1) {
        if (tid < ks) g_kc80[tid] = buf[tid] * inv;
    } else {
        if (tid < ks) g_kc250[tid] = buf[tid] * inv;
    }
}

// ---------------- 2: downsample s=2 (clip fused) ----------------
__global__ void ds2_k(const float* __restrict__ in) {
    int i = blockIdx.x * 256 + threadIdx.x;
    int img = i >> 18;
    int r   = i & (C2 * C2 - 1);
    int cy = r >> 9, cx = r & 511;
    size_t base = (size_t)img * HH * WW + (size_t)(2 * cy) * WW;
    float2 a = ((const float2*)(in + base))[cx];
    float2 b = ((const float2*)(in + base + WW))[cx];
    float s =
        fminf(fmaxf(a.x, EPSV), 1.f) + fminf(fmaxf(a.y, EPSV), 1.f) +
        fminf(fmaxf(b.x, EPSV), 1.f) + fminf(fmaxf(b.y, EPSV), 1.f);
    g_s2a[i] = s * 0.25f;
}

// ---------------- 3: downsample s2 -> s8 and s8 -> s16 ----------------
__global__ void ds816_k() {
    int i = blockIdx.x * 256 + threadIdx.x;
    int img = i / (C16 * C16);
    int r   = i % (C16 * C16);
    int cy = r >> 6, cx = r & 63;
    const float* s2 = g_s2a + (size_t)img * C2 * C2;
    float* c8 = g_c8a + (size_t)img * C8 * C8;
    float tot = 0.f;
#pragma unroll
    for (int dy2 = 0; dy2 < 2; dy2++)
#pragma unroll
        for (int dx2 = 0; dx2 < 2; dx2++) {
            float s = 0.f;
            int y0 = 8 * cy + 4 * dy2, x0 = 8 * cx + 4 * dx2;
#pragma unroll
            for (int a = 0; a < 4; a++)
#pragma unroll
                for (int b = 0; b < 4; b++)
                    s += s2[(y0 + a) * C2 + x0 + b];
            c8[(2 * cy + dy2) * C8 + 2 * cx + dx2] = s * (1.0f / 16.0f);
            tot += s;
        }
    g_c16a[i] = tot * (1.0f / 64.0f);
}

// ---------------- 4: batched coarse vertical convs (8 rows/thread ring) ----------------
// blocks: [0,8) sigma80 on C8, [8,10) sigma250 on C16
__global__ void __launch_bounds__(256)
cconv_v_k() {
    int bx = blockIdx.x, img = blockIdx.y, tid = threadIdx.x;
    const float* kc; const float* src; float* dst; int C, ks, p;
    if (bx < 8) {
        kc = g_kc80;  C = C8;  ks = KS80;  p = P80;
        src = g_c8a + (size_t)img * C8 * C8;  dst = g_c8b + (size_t)img * C8 * C8;
    } else {
        bx -= 8;
        kc = g_kc250; C = C16; ks = KS250; p = P250;
        src = g_c16a + (size_t)img * C16 * C16; dst = g_c16b + (size_t)img * C16 * C16;
    }
    __shared__ float kkp[120];
    for (int i = tid; i < 120; i += 256) kkp[i] = (i >= 8 && i < 8 + ks) ? kc[i - 8] : 0.f;
    __syncthreads();

    int idx = bx * 256 + tid;
    int cx  = idx % C;
    int cy0 = (idx / C) * 8;
    int T2 = ((ks + 8 + 7) / 8) * 8;         // 72 / 104

    float acc[8], kw[8];
#pragma unroll
    for (int j = 0; j < 8; j++) { acc[j] = 0.f; kw[j] = 0.f; }
    kw[0] = kkp[8];
    float v = src[reflC(cy0 - p, C) * C + cx];

    for (int tb = 0; tb < T2; tb += 8) {
#pragma unroll
        for (int u = 0; u < 8; u++) {
            float kn = kkp[8 + tb + u + 1];
            float vn = src[reflC(cy0 - p + tb + u + 1, C) * C + cx];
#pragma unroll
            for (int j = 0; j < 8; j++)
                acc[j] += kw[(u - j) & 7] * v;
            kw[(u + 1) & 7] = kn;
            v = vn;
        }
    }
#pragma unroll
    for (int j = 0; j < 8; j++) dst[(cy0 + j) * C + cx] = acc[j];
}

// ---------------- 5: batched coarse horizontal convs ----------------
// blocks: [0,64) sigma80 on C8, [64,80) sigma250 on C16
__global__ void __launch_bounds__(256)
cconv_h_k() {
    int bx = blockIdx.x, img = blockIdx.y, tid = threadIdx.x;
    if (bx < 64) {
        int idx = bx * 256 + tid;
        int y = idx / C8, x = idx % C8;
        const float* s0 = g_c8b + (size_t)img * C8 * C8;
        float a = 0.f;
        for (int t = 0; t < KS80; t++)
            a += g_kc80[t] * s0[y * C8 + reflC(x - P80 + t, C8)];
        g_c8a[(size_t)img * C8 * C8 + idx] = a;
    } else {
        int idx = (bx - 64) * 256 + tid;
        int y = idx / C16, x = idx % C16;
        const float* s0 = g_c16b + (size_t)img * C16 * C16;
        float a = 0.f;
        for (int t = 0; t < KS250; t++)
            a += g_kc250[t] * s0[y * C16 + reflC(x - P250 + t, C16)];
        g_c16a[(size_t)img * C16 * C16 + idx] = a;
    }
}

// ---------------- 6: merge sigma80 + sigma250 log fields onto s2 grid ----------------
__global__ void merge_k() {
    int i = blockIdx.x * 256 + threadIdx.x;
    int img = i >> 18;
    int r   = i & (C2 * C2 - 1);
    int cy = r >> 9, cx = r & 511;
    float yf = 2.f * cy + 0.5f, xf = 2.f * cx + 0.5f;
    float u80  = bilerpF(g_c8a  + (size_t)img * C8 * C8,   C8,  0.125f,  3.5f, yf, xf);
    float u250 = bilerpF(g_c16a + (size_t)img * C16 * C16, C16, 0.0625f, 7.5f, yf, xf);
    g_s2b[i] = logf(fmaxf(u80, EPSV)) + logf(fmaxf(u250, EPSV));
}

// ---------------- 7: fine vertical conv (sigma=15 exact), ring buffer, f32x2 ----------------
template<int DOCLIP>
__global__ void __launch_bounds__(128, 4)
conv_v_k(const u64* __restrict__ src, u64* __restrict__ dst) {
    __shared__ u64 ksh[KLEN15];
    for (int i = threadIdx.x; i < KLEN15; i += 128) ksh[i] = g_kern2u[i];
    __syncthreads();

    int cp = blockIdx.x * 128 + threadIdx.x;       // column-pair 0..511
    int r0 = blockIdx.y * RR;
    const u64* s0 = src + (size_t)blockIdx.z * (HH * WW / 2);

    u64 acc[RR], cw[RR];
#pragma unroll
    for (int j = 0; j < RR; j++) { acc[j] = 0ULL; cw[j] = 0ULL; }

    cw[0] = ksh[16];
    u64 v = s0[(size_t)refl1024(r0 - P15) * 512 + cp];
    if (DOCLIP) v = clip2(v);

    for (int step = 0; step < S2_15; step += RR) {
#pragma unroll
        for (int u = 0; u < RR; u++) {
            u64 kn = ksh[16 + step + u + 1];
            int sn = r0 - P15 + step + u + 1;
            u64 vn = s0[(size_t)refl1024(sn) * 512 + cp];
#pragma unroll
            for (int j = 0; j < RR; j++)
                acc[j] = ffma2(cw[(u - j) & (RR - 1)], v, acc[j]);
            cw[(u + 1) & (RR - 1)] = kn;
            v = DOCLIP ? clip2(vn) : vn;
        }
    }

    u64* d0 = dst + (size_t)blockIdx.z * (HH * WW / 2);
#pragma unroll
    for (int j = 0; j < RR; j++) d0[(size_t)(r0 + j) * 512 + cp] = acc[j];
}

// ---------------- 8: tiled transpose ----------------
__global__ void transpose_k(const float* __restrict__ src, float* __restrict__ dst) {
    __shared__ float tile[32][33];
    size_t base = (size_t)blockIdx.z * HH * WW;
    int x  = blockIdx.x * 32 + threadIdx.x;
    int y0 = blockIdx.y * 32 + threadIdx.y;
#pragma unroll
    for (int dy = 0; dy < 32; dy += 8)
        tile[threadIdx.y + dy][threadIdx.x] = src[base + (size_t)(y0 + dy) * WW + x];
    __syncthreads();
    int x2 = blockIdx.y * 32 + threadIdx.x;
    int y2 = blockIdx.x * 32 + threadIdx.y;
#pragma unroll
    for (int dy = 0; dy < 32; dy += 8)
        dst[base + (size_t)(y2 + dy) * WW + x2] = tile[threadIdx.x][threadIdx.y + dy];
}

// ---------------- 9: fused finalize + gradient reduction ----------------
// b15T holds blur15 stored transposed. 32x32 owned + 1 halo (right/bottom).
__global__ void __launch_bounds__(256)
final_k(const float* __restrict__ in, const float* __restrict__ b15T,
        float* __restrict__ orefl, float* __restrict__ oil) {
    __shared__ float sB[33][34];
    __shared__ float sR[33][34];
    __shared__ float sI[33][34];
    __shared__ float warpred[8][4];

    int img = blockIdx.z;
    size_t base = (size_t)img * HH * WW;
    const float* L2 = g_s2b + (size_t)img * C2 * C2;
    int X0 = blockIdx.x * 32;
    int Y0 = blockIdx.y * 32;
    int tid = threadIdx.x;

    // A: load b15 (transposed storage) -> sB[y][x]; coalesced along y.
    for (int idx = tid; idx < 33 * 33; idx += 256) {
        int xo = idx / 33, yo = idx % 33;
        int gx = min(X0 + xo, HH - 1);
        int gy = min(Y0 + yo, HH - 1);
        sB[yo][xo] = b15T[base + (size_t)gx * WW + gy];
    }
    __syncthreads();

    // B: refl / il for the 33x33 halo tile.
    for (int idx = tid; idx < 33 * 33; idx += 256) {
        int yo = idx / 33, xo = idx % 33;
        int gy = min(Y0 + yo, HH - 1);
        int gx = min(X0 + xo, WW - 1);
        float b15 = sB[yo][xo];
        float l2  = bilerpF(L2, C2, 0.5f, 0.5f, (float)gy, (float)gx);
        float il3 = (logf(fmaxf(b15, EPSV)) + l2) * (1.0f / 3.0f);
        float xv = in[base + (size_t)gy * WW + gx];
        float lmax  = logf(fmaxf(xv, EPSV));
        float lclip = fminf(lmax, 0.0f);          // log(clip(x, eps, 1))
        float refl = lclip - il3;
        sR[yo][xo] = refl;
        sI[yo][xo] = lmax - refl;
    }
    __syncthreads();

    // C: write owned 32x32 + accumulate gradient abs-sums (float).
    float a0 = 0.f, a1 = 0.f, a2 = 0.f, a3 = 0.f;
    for (int idx = tid; idx < 32 * 32; idx += 256) {
        int yo = idx >> 5, xo = idx & 31;
        int gy = Y0 + yo, gx = X0 + xo;
        size_t o = base + (size_t)gy * WW + gx;
        float r = sR[yo][xo], i = sI[yo][xo];
        orefl[o] = r;
        oil[o]   = i;
        if (gx < WW - 1) { a0 += fabsf(r - sR[yo][xo + 1]); a2 += fabsf(i - sI[yo][xo + 1]); }
        if (gy < HH - 1) { a1 += fabsf(r - sR[yo + 1][xo]); a3 += fabsf(i - sI[yo + 1][xo]); }
    }

#pragma unroll
    for (int s = 16; s > 0; s >>= 1) {
        a0 += __shfl_down_sync(0xffffffffu, a0, s);
        a1 += __shfl_down_sync(0xffffffffu, a1, s);
        a2 += __shfl_down_sync(0xffffffffu, a2, s);
        a3 += __shfl_down_sync(0xffffffffu, a3, s);
    }
    int wid = tid >> 5, lid = tid & 31;
    if (lid == 0) {
        warpred[wid][0] = a0; warpred[wid][1] = a1;
        warpred[wid][2] = a2; warpred[wid][3] = a3;
    }
    __syncthreads();
    if (tid == 0) {
        double t0 = 0, t1 = 0, t2 = 0, t3 = 0;
#pragma unroll
        for (int w = 0; w < 8; w++) {
            t0 += (double)warpred[w][0]; t1 += (double)warpred[w][1];
            t2 += (double)warpred[w][2]; t3 += (double)warpred[w][3];
        }
        int bid = (img * 32 + blockIdx.y) * 32 + blockIdx.x;
        g_part[bid * 4 + 0] = t0; g_part[bid * 4 + 1] = t1;
        g_part[bid * 4 + 2] = t2; g_part[bid * 4 + 3] = t3;
    }
}

// ---------------- 10: scalar reduction ----------------
__global__ void scalar_k(float* __restrict__ out) {
    __shared__ double sd[256];
    __shared__ double tot[4];
    int tid = threadIdx.x;
    double s[4] = {0, 0, 0, 0};
    for (int i = tid; i < NTILE; i += 256) {
        s[0] += g_part[i * 4 + 0];
        s[1] += g_part[i * 4 + 1];
        s[2] += g_part[i * 4 + 2];
        s[3] += g_part[i * 4 + 3];
    }
    for (int k = 0; k < 4; k++) {
        sd[tid] = s[k];
        __syncthreads();
        for (int st = 128; st > 0; st >>= 1) {
            if (tid < st) sd[tid] += sd[tid + st];
            __syncthreads();
        }
        if (tid == 0) tot[k] = sd[0];
        __syncthreads();
    }
    if (tid == 0) {
        double denx = (double)NIMG * HH * (WW - 1);
        double deny = (double)NIMG * (HH - 1) * WW;
        double detail = tot[0] / denx + tot[1] / deny;
        double smooth = tot[2] / denx + tot[3] / deny;
        out[0] = (float)(0.0 * detail + 1.0 * smooth);  // DETAIL_W=0, ILLUM_W=1
        out[1] = (float)detail;
        out[2] = (float)smooth;
    }
}

// ---------------- launch ----------------
extern "C" void kernel_launch(void* const* d_in, const int* in_sizes, int n_in,
                              void* d_out, int out_size) {
    const float* input = (const float*)d_in[0];
    float* out = (float*)d_out;

    float *tmpP = nullptr, *tmpTP = nullptr;
    cudaGetSymbolAddress((void**)&tmpP,  g_tmp);
    cudaGetSymbolAddress((void**)&tmpTP, g_tmpT);

    init_kernels_k<<<3, 512>>>();

    // coarse path: s=2 box chain -> sigma80/sigma250 coarse blurs -> merged logs
    ds2_k<<<N2 / 256, 256>>>(input);
    ds816_k<<<N16 / 256, 256>>>();
    cconv_v_k<<<dim3(10, NIMG), 256>>>();
    cconv_h_k<<<dim3(80, NIMG), 256>>>();
    merge_k<<<N2 / 256, 256>>>();

    // fine path: exact sigma=15 separable conv (clip fused into pass 1)
    dim3 cg(4, 64, NIMG);
    conv_v_k<1><<<cg, 128>>>((const u64*)input, (u64*)tmpP);
    transpose_k<<<dim3(32, 32, NIMG), dim3(32, 8)>>>(tmpP, tmpTP);
    conv_v_k<0><<<cg, 128>>>((const u64*)tmpTP, (u64*)tmpP);  // -> blur15 transposed

    // fused finalize (+gradient reduction) and scalar pass
    final_k<<<dim3(32, 32, NIMG), 256>>>(input, tmpP, out + 3, out + 3 + NPIX);
    scalar_k<<<1, 256>>>(out);
}